// round 16
// baseline (speedup 1.0000x reference)
#include <cuda_runtime.h>
#include <cuda_fp16.h>
#include <cstdint>

#define BB   8
#define QQ   2048
#define KSEQ 2048
#define DIM  512

// ---------------- device scratch (fp16 planes) -------------------------------
__device__ __align__(1024) __half g_qsp [16384u*512u];       // query hi
__device__ __align__(1024) __half g_wsp [2u*512u*512u];      // W row-major hi+lo
__device__ __align__(1024) __half g_ksp [16384u*512u];       // key hi
__device__ __align__(1024) __half g_kwsp[16384u*512u];       // kW (compacted) hi
__device__ __align__(1024) __half g_vtsp[4096u*2048u];       // gathered value^T hi
__device__ __align__(1024) __half g_dssp[16384u*2048u];      // compacted dist hi (zero-init)
__device__ __align__(1024) float  g_scf [16384u*2048u];      // compacted scores fp32
__device__ int g_kidx[BB * KSEQ];
__device__ int g_rank[BB * KSEQ];
__device__ int g_cnt [BB];
__device__ int g_nch3[BB];

__device__ __forceinline__ uint32_t smem_u32(const void* p) {
    uint32_t a;
    asm("{ .reg .u64 t; cvta.to.shared.u64 t, %1; cvt.u32.u64 %0, t; }"
        : "=r"(a) : "l"(p));
    return a;
}
__device__ __forceinline__ void cp16(uint32_t dst, const void* src) {
    asm volatile("cp.async.cg.shared.global [%0], [%1], 16;"
                 :: "r"(dst), "l"(src) : "memory");
}
__device__ __forceinline__ void cp_commit() {
    asm volatile("cp.async.commit_group;" ::: "memory");
}
__device__ __forceinline__ void cp_wait1() {
    asm volatile("cp.async.wait_group 1;" ::: "memory");
}
__device__ __forceinline__ void cp_wait0() {
    asm volatile("cp.async.wait_group 0;" ::: "memory");
}
__device__ __forceinline__ void ldmx4(uint32_t r[4], uint32_t addr) {
    asm volatile("ldmatrix.sync.aligned.m8n8.x4.shared.b16 {%0,%1,%2,%3}, [%4];"
                 : "=r"(r[0]), "=r"(r[1]), "=r"(r[2]), "=r"(r[3]) : "r"(addr));
}
__device__ __forceinline__ void mma16816(float c[4], const uint32_t a[4], const uint32_t* b) {
    asm volatile("mma.sync.aligned.m16n8k16.row.col.f32.f16.f16.f32 "
                 "{%0,%1,%2,%3}, {%4,%5,%6,%7}, {%8,%9}, {%0,%1,%2,%3};"
                 : "+f"(c[0]), "+f"(c[1]), "+f"(c[2]), "+f"(c[3])
                 : "r"(a[0]), "r"(a[1]), "r"(a[2]), "r"(a[3]), "r"(b[0]), "r"(b[1]));
}
__device__ __forceinline__ void splitf(float v, __half& h, __half& l) {
    h = __float2half_rn(v);
    l = __float2half_rn(v - __half2float(h));
}

// ---------------- fp16 mma.sync GEMM (batched over blockIdx.z) ---------------
// NT=2: C = A_h @ (B_h + B_l)^T.   NT=1: C = A_h @ B_h^T.
// BK=32, 3-stage cp.async pipeline, one barrier per chunk.
#define TILEB 10240
#define NSTG  3

// EPI: 0 = fp16 hi out (kW), 1 = scale fp32 (scores), 2 = fp32 (ctx)
template <int EPI, int NT>
__global__ __launch_bounds__(256, 2) void mma_gemm(
    const __half* __restrict__ A, int lda, long long Abstride,
    const __half* __restrict__ B, long long Bplane, int ldb, long long Bbstride,
    int nch_in,
    float* __restrict__ outF,
    __half* __restrict__ outH, long long obstride,
    float scale, int ldc,
    const int* __restrict__ agidx,
    const int* __restrict__ mcnt, const int* __restrict__ ncnt,
    const int* __restrict__ nchp)
{
    constexpr uint32_t SSTG = (NT + 1) * TILEB;   // stage stride: A + Bh (+ Bl)

    const int bz = blockIdx.z;
    if (mcnt && (int)(blockIdx.y * 128) >= mcnt[bz]) return;
    if (ncnt && (int)(blockIdx.x * 128) >= ncnt[bz]) return;
    const int nch = nchp ? nchp[bz] : nch_in;

    extern __shared__ char smem[];
    const uint32_t sb = smem_u32(smem);

    const int tid = threadIdx.x;
    const int lane = tid & 31, wrp = tid >> 5;
    const int wm = (wrp >> 2) * 64, wn = (wrp & 3) * 32;

    const int r0 = tid >> 2, c0 = (tid & 3) * 8;

    const __half* Ab = A + (long long)bz * Abstride;
    const __half* Bb = B + (long long)bz * Bbstride;

    int ar0 = blockIdx.y * 128 + r0, ar1 = ar0 + 64;
    if (agidx) { ar0 = agidx[bz * KSEQ + ar0]; ar1 = agidx[bz * KSEQ + ar1]; }
    const __half* a_src0 = Ab + (long long)ar0 * lda + c0;
    const __half* a_src1 = Ab + (long long)ar1 * lda + c0;

    const __half* b_src0 = Bb + (long long)(blockIdx.x * 128 + r0) * ldb + c0;
    const __half* b_src1 = b_src0 + (long long)64 * ldb;

    const int g = lane >> 3, lr = lane & 7;
    const uint32_t aoff = (uint32_t)(wm + (g & 1) * 8 + lr) * 80 + ((g >> 1) * 16);
    const uint32_t boff = (uint32_t)(wn + ((g >> 1) & 1) * 8 + lr) * 80 + ((g & 1) * 16);

    float acc[4][4][4];
    #pragma unroll
    for (int mt = 0; mt < 4; mt++)
        #pragma unroll
        for (int nt = 0; nt < 4; nt++)
            #pragma unroll
            for (int i = 0; i < 4; i++) acc[mt][nt][i] = 0.f;

    auto load_stage = [&](int buf, int k0) {
        const uint32_t st = sb + buf * SSTG;
        const uint32_t d0 = (uint32_t)r0 * 80 + (c0 * 2);
        const uint32_t d1 = (uint32_t)(r0 + 64) * 80 + (c0 * 2);
        cp16(st + d0, a_src0 + k0);
        cp16(st + d1, a_src1 + k0);
        cp16(st + TILEB + d0, b_src0 + k0);
        cp16(st + TILEB + d1, b_src1 + k0);
        if (NT == 2) {
            cp16(st + 2 * TILEB + d0, b_src0 + k0 + Bplane);
            cp16(st + 2 * TILEB + d1, b_src1 + k0 + Bplane);
        }
        cp_commit();
    };

    load_stage(0, 0);
    load_stage(1, 32);

    for (int kt = 0; kt < nch; ++kt) {
        if (kt + 1 < nch) cp_wait1(); else cp_wait0();
        __syncthreads();
        // prefetch chunk kt+2 into buffer (kt+2)%3 (held chunk kt-1, whose
        // consumers all passed the barrier above)
        if (kt + 2 < nch) load_stage((kt + 2) % NSTG, (kt + 2) * 32);

        const uint32_t st = sb + (kt % NSTG) * SSTG;
        #pragma unroll
        for (int kk = 0; kk < 2; kk++) {
            uint32_t ah[4][4], bh[2][4], bl[2][4];
            #pragma unroll
            for (int mt = 0; mt < 4; mt++)
                ldmx4(ah[mt], st + mt * (16 * 80) + kk * 32 + aoff);
            #pragma unroll
            for (int nt2 = 0; nt2 < 2; nt2++) {
                const uint32_t bd = st + TILEB + nt2 * (16 * 80) + kk * 32 + boff;
                ldmx4(bh[nt2], bd);
                if (NT == 2) ldmx4(bl[nt2], bd + TILEB);
            }
            #pragma unroll
            for (int mt = 0; mt < 4; mt++)
                #pragma unroll
                for (int nt = 0; nt < 4; nt++) {
                    const uint32_t* ph = &bh[nt >> 1][(nt & 1) * 2];
                    mma16816(acc[mt][nt], ah[mt], ph);
                    if (NT == 2) {
                        const uint32_t* pl = &bl[nt >> 1][(nt & 1) * 2];
                        mma16816(acc[mt][nt], ah[mt], pl);
                    }
                }
        }
    }

    // ---- epilogue ----
    float* outFb = outF + (long long)bz * obstride;
    __half* outHb = outH + (long long)bz * obstride;
    const int rbase = blockIdx.y * 128 + wm + (lane >> 2);
    const int cbase = blockIdx.x * 128 + wn + ((lane & 3) << 1);

    #pragma unroll
    for (int mt = 0; mt < 4; mt++) {
        #pragma unroll
        for (int nt = 0; nt < 4; nt++) {
            const int col = cbase + nt * 8;
            #pragma unroll
            for (int h = 0; h < 2; h++) {
                const int row = rbase + mt * 16 + h * 8;
                float v0 = acc[mt][nt][2 * h], v1 = acc[mt][nt][2 * h + 1];
                const long long o = (long long)row * ldc + col;
                if (EPI == 0) {
                    *(__half2*)(outHb + o) =
                        __halves2half2(__float2half_rn(v0), __float2half_rn(v1));
                } else if (EPI == 1) {
                    *(float2*)(outFb + o) = make_float2(v0 * scale, v1 * scale);
                } else {
                    *(float2*)(outFb + o) = make_float2(v0, v1);
                }
            }
        }
    }
}

// ---------------- mask compaction --------------------------------------------
__global__ void compact_kernel(const int* __restrict__ mask)
{
    const int b = blockIdx.x;
    const int tid = threadIdx.x;
    const int* mrow = mask + b * KSEQ;
    int* kid = g_kidx + b * KSEQ;
    int* rnk = g_rank + b * KSEQ;

    #pragma unroll
    for (int e = 0; e < 8; e++) kid[tid * 8 + e] = 0;
    __syncthreads();

    int m[8], lsum = 0;
    #pragma unroll
    for (int e = 0; e < 8; e++) { m[e] = mrow[tid * 8 + e]; lsum += (m[e] != 0); }

    int s = lsum;
    #pragma unroll
    for (int o = 1; o < 32; o <<= 1) {
        int n = __shfl_up_sync(0xffffffffu, s, o);
        if ((tid & 31) >= o) s += n;
    }
    __shared__ int wsum[8];
    if ((tid & 31) == 31) wsum[tid >> 5] = s;
    __syncthreads();
    int woff = 0, total = 0;
    #pragma unroll
    for (int w = 0; w < 8; w++) {
        if (w < (tid >> 5)) woff += wsum[w];
        total += wsum[w];
    }
    int running = woff + s - lsum;

    #pragma unroll
    for (int e = 0; e < 8; e++) {
        const int p = tid * 8 + e;
        if (m[e]) { kid[running] = p; rnk[p] = running; running++; }
        else rnk[p] = 0;
    }
    if (tid == 0) { g_cnt[b] = total; g_nch3[b] = (total + 31) / 32; }
}

// ---------------- elementwise splits ------------------------------------------
// grid.y = 2 selects tensor (0: query->qsp, 1: key->ksp), hi plane only
__global__ void split_qk_kernel(const float* __restrict__ q, const float* __restrict__ k)
{
    const float* in = blockIdx.y ? k : q;
    __half* out = blockIdx.y ? g_ksp : g_qsp;
    const long long i = ((long long)blockIdx.x * blockDim.x + threadIdx.x) * 4;
    float4 v = *(const float4*)(in + i);
    out[i]     = __float2half_rn(v.x);
    out[i + 1] = __float2half_rn(v.y);
    out[i + 2] = __float2half_rn(v.z);
    out[i + 3] = __float2half_rn(v.w);
}

template <int LO>
__global__ void split_kernel(const float* __restrict__ in, __half* __restrict__ out,
                             long long plane)
{
    const long long i = ((long long)blockIdx.x * blockDim.x + threadIdx.x) * 4;
    float4 v = *(const float4*)(in + i);
    __half h0, l0, h1, l1, h2, l2, h3, l3;
    splitf(v.x, h0, l0); splitf(v.y, h1, l1); splitf(v.z, h2, l2); splitf(v.w, h3, l3);
    *(__half2*)(out + i)     = __halves2half2(h0, h1);
    *(__half2*)(out + i + 2) = __halves2half2(h2, h3);
    if (LO) {
        *(__half2*)(out + plane + i)     = __halves2half2(l0, l1);
        *(__half2*)(out + plane + i + 2) = __halves2half2(l2, l3);
    }
}

// transpose [R,C] -> [C,R] per batch with row gather, hi plane only
__global__ void tsplit_kernel(const float* __restrict__ in, __half* __restrict__ out,
                              int R, int C, const int* __restrict__ gidx)
{
    __shared__ float t[32][33];
    const int bz = blockIdx.z;
    const long long boff = (long long)bz * R * C;
    const int x = blockIdx.x * 32 + threadIdx.x;
    #pragma unroll
    for (int i = 0; i < 4; ++i) {
        const int y = blockIdx.y * 32 + threadIdx.y + i * 8;
        const int ys = gidx ? gidx[bz * R + y] : y;
        t[threadIdx.y + i * 8][threadIdx.x] = in[boff + (long long)ys * C + x];
    }
    __syncthreads();
    const int xo = blockIdx.y * 32 + threadIdx.x;
    #pragma unroll
    for (int i = 0; i < 4; ++i) {
        const int yo = blockIdx.x * 32 + threadIdx.y + i * 8;
        const float v = t[threadIdx.x][threadIdx.y + i * 8];
        out[boff + (long long)yo * R + xo] = __float2half_rn(v);
    }
}

// ---------------- compacted softmax + scatter (cn-predicated traffic) --------
__global__ void softmax_scatter_kernel(const float* __restrict__ sc,
                                       float* __restrict__ dist,
                                       __half* __restrict__ ds,
                                       const int* __restrict__ mask,
                                       const int* __restrict__ rank,
                                       const int* __restrict__ cntp)
{
    const int bz = blockIdx.y;
    const long long row = (long long)bz * QQ + blockIdx.x;
    const int tid = threadIdx.x;
    const int cn = cntp[bz];
    const float* p = sc + row * (long long)KSEQ;
    const int* mrow = mask + (long long)bz * KSEQ;
    const int* rrow = rank + (long long)bz * KSEQ;

    __shared__ float sm[2048];
    __shared__ float red[8];

    const int j0 = tid * 4, j1 = j0 + 1024;
    float4 v0 = make_float4(0.f, 0.f, 0.f, 0.f);
    float4 v1 = make_float4(0.f, 0.f, 0.f, 0.f);
    if (j0 < cn) v0 = ((const float4*)p)[tid];
    if (j1 < cn) v1 = ((const float4*)p)[tid + 256];

    const float NEG = -1e30f;
    float m = NEG;
    m = fmaxf(m, (j0 + 0 < cn) ? v0.x : NEG);
    m = fmaxf(m, (j0 + 1 < cn) ? v0.y : NEG);
    m = fmaxf(m, (j0 + 2 < cn) ? v0.z : NEG);
    m = fmaxf(m, (j0 + 3 < cn) ? v0.w : NEG);
    m = fmaxf(m, (j1 + 0 < cn) ? v1.x : NEG);
    m = fmaxf(m, (j1 + 1 < cn) ? v1.y : NEG);
    m = fmaxf(m, (j1 + 2 < cn) ? v1.z : NEG);
    m = fmaxf(m, (j1 + 3 < cn) ? v1.w : NEG);
    #pragma unroll
    for (int o = 16; o > 0; o >>= 1) m = fmaxf(m, __shfl_xor_sync(0xffffffffu, m, o));
    if ((tid & 31) == 0) red[tid >> 5] = m;
    __syncthreads();
    m = red[0];
    #pragma unroll
    for (int i = 1; i < 8; i++) m = fmaxf(m, red[i]);
    __syncthreads();

    float e00 = (j0 + 0 < cn) ? __expf(v0.x - m) : 0.f;
    float e01 = (j0 + 1 < cn) ? __expf(v0.y - m) : 0.f;
    float e02 = (j0 + 2 < cn) ? __expf(v0.z - m) : 0.f;
    float e03 = (j0 + 3 < cn) ? __expf(v0.w - m) : 0.f;
    float e10 = (j1 + 0 < cn) ? __expf(v1.x - m) : 0.f;
    float e11 = (j1 + 1 < cn) ? __expf(v1.y - m) : 0.f;
    float e12 = (j1 + 2 < cn) ? __expf(v1.z - m) : 0.f;
    float e13 = (j1 + 3 < cn) ? __expf(v1.w - m) : 0.f;

    float s = e00 + e01 + e02 + e03 + e10 + e11 + e12 + e13;
    #pragma unroll
    for (int o = 16; o > 0; o >>= 1) s += __shfl_xor_sync(0xffffffffu, s, o);
    if ((tid & 31) == 0) red[tid >> 5] = s;
    __syncthreads();
    float tot = red[0];
    #pragma unroll
    for (int i = 1; i < 8; i++) tot += red[i];
    const float inv = 1.0f / tot;

    e00 *= inv; e01 *= inv; e02 *= inv; e03 *= inv;
    e10 *= inv; e11 *= inv; e12 *= inv; e13 *= inv;

    *(float4*)&sm[j0] = make_float4(e00, e01, e02, e03);
    *(float4*)&sm[j1] = make_float4(e10, e11, e12, e13);

    const long long b0o = row * (long long)KSEQ + j0;
    const long long b1o = row * (long long)KSEQ + j1;
    if (j0 < cn) {
        *(__half2*)(ds + b0o)     = __halves2half2(__float2half_rn(e00), __float2half_rn(e01));
        *(__half2*)(ds + b0o + 2) = __halves2half2(__float2half_rn(e02), __float2half_rn(e03));
    }
    if (j1 < cn) {
        *(__half2*)(ds + b1o)     = __halves2half2(__float2half_rn(e10), __float2half_rn(e11));
        *(__half2*)(ds + b1o + 2) = __halves2half2(__float2half_rn(e12), __float2half_rn(e13));
    }

    __syncthreads();

    float* drow = dist + row * (long long)KSEQ;
    #pragma unroll
    for (int h = 0; h < 2; h++) {
        const int idx = tid + h * 256;
        int4 mk = ((const int4*)mrow)[idx];
        int4 rk = ((const int4*)rrow)[idx];
        float4 o;
        o.x = mk.x ? sm[rk.x] : 0.f;
        o.y = mk.y ? sm[rk.y] : 0.f;
        o.z = mk.z ? sm[rk.z] : 0.f;
        o.w = mk.w ? sm[rk.w] : 0.f;
        ((float4*)drow)[idx] = o;
    }
}

// ---------------- host side ---------------------------------------------------
#define SMEM2 (NSTG * 3 * TILEB)   // 2-term kernel
#define SMEM1 (NSTG * 2 * TILEB)   // 1-term kernel

struct Ctx {
    __half *q, *w, *k, *kw, *vt, *ds;
    float* scf;
    int *kidx, *rank, *cnt, *nch3;
    bool ready;
};
static Ctx& get_ctx()
{
    static Ctx c = {};
    if (!c.ready) {
        cudaGetSymbolAddress((void**)&c.q,    g_qsp);
        cudaGetSymbolAddress((void**)&c.w,    g_wsp);
        cudaGetSymbolAddress((void**)&c.k,    g_ksp);
        cudaGetSymbolAddress((void**)&c.kw,   g_kwsp);
        cudaGetSymbolAddress((void**)&c.vt,   g_vtsp);
        cudaGetSymbolAddress((void**)&c.ds,   g_dssp);
        cudaGetSymbolAddress((void**)&c.scf,  g_scf);
        cudaGetSymbolAddress((void**)&c.kidx, g_kidx);
        cudaGetSymbolAddress((void**)&c.rank, g_rank);
        cudaGetSymbolAddress((void**)&c.cnt,  g_cnt);
        cudaGetSymbolAddress((void**)&c.nch3, g_nch3);
        cudaFuncSetAttribute(mma_gemm<0, 2>, cudaFuncAttributeMaxDynamicSharedMemorySize, SMEM2);
        cudaFuncSetAttribute(mma_gemm<1, 1>, cudaFuncAttributeMaxDynamicSharedMemorySize, SMEM1);
        cudaFuncSetAttribute(mma_gemm<2, 1>, cudaFuncAttributeMaxDynamicSharedMemorySize, SMEM1);
        c.ready = true;
    }
    return c;
}

extern "C" void kernel_launch(void* const* d_in, const int* in_sizes, int n_in,
                              void* d_out, int out_size)
{
    const float* query = (const float*)d_in[0];
    const float* key   = (const float*)d_in[1];
    const float* value = (const float*)d_in[2];
    const int*   mask  = (const int*)d_in[3];
    const float* W     = (const float*)d_in[4];

    float* ctx  = (float*)d_out;                               // [B,Q,D]
    float* dist = ctx + (long long)BB * QQ * DIM;              // [B,Q,K]

    Ctx& C = get_ctx();
    const float scale = 0.044194173824159216f;                 // 1/sqrt(512)

    const long long PW = (long long)512 * 512;
    const long long SB = (long long)QQ * 512;      // per-batch stride, 512-wide
    const long long SD = (long long)QQ * KSEQ;     // per-batch stride, 2048-wide
    const long long SV = (long long)512 * 2048;    // vt per-batch stride

    // single default-stream chain; each launch fills the chip via z-batching
    compact_kernel<<<BB, 256>>>(mask);
    split_qk_kernel<<<dim3(8192, 2), 256>>>(query, key);
    split_kernel<1><<<256, 256>>>(W, C.w, PW);
    tsplit_kernel<<<dim3(16, 64, 8), dim3(32, 8)>>>(value, C.vt, 2048, 512, C.kidx);

    // GEMM1 (2-term): kW = gather(k_h) @ (W_h+W_l)^T, M = cnt[b] -> fp16 hi
    mma_gemm<0, 2><<<dim3(4, 16, BB), 256, SMEM2>>>(
        C.k, 512, SB, C.w, PW, 512, 0, 16,
        nullptr, C.kw, SB, 0.f, 512,
        C.kidx, C.cnt, nullptr, nullptr);

    // GEMM2 (1-term): scores = q_h @ kW_h^T * scale, N = cnt[b]
    mma_gemm<1, 1><<<dim3(16, 16, BB), 256, SMEM1>>>(
        C.q, 512, SB, C.kw, 0, 512, SB, 16,
        C.scf, nullptr, SD, scale, 2048,
        nullptr, nullptr, C.cnt, nullptr);

    // softmax + scatter + fp16 hi split, all batches
    softmax_scatter_kernel<<<dim3(QQ, BB), 256>>>(
        C.scf, dist, C.ds, mask, C.rank, C.cnt);

    // GEMM3 (1-term): ctx = dist_h @ vt_h^T, K = cnt[b]
    mma_gemm<2, 1><<<dim3(4, 16, BB), 256, SMEM1>>>(
        C.ds, 2048, SD, C.vt, 0, 2048, SV, 64,
        ctx, nullptr, SB, 0.f, 512,
        nullptr, nullptr, nullptr, C.nch3);
}

// round 17
// speedup vs baseline: 1.5094x; 1.5094x over previous
#include <cuda_runtime.h>
#include <cuda_fp16.h>
#include <cstdint>

#define BB   8
#define QQ   2048
#define KSEQ 2048
#define DIM  512

// ---------------- device scratch (fp16 planes) -------------------------------
__device__ __align__(1024) __half g_qsp [16384u*512u];       // query hi
__device__ __align__(1024) __half g_wsp [2u*512u*512u];      // W row-major hi+lo
__device__ __align__(1024) __half g_ksp [16384u*512u];       // key hi
__device__ __align__(1024) __half g_kwsp[16384u*512u];       // kW (compacted) hi
__device__ __align__(1024) __half g_vtsp[4096u*2048u];       // gathered value^T hi
__device__ __align__(1024) __half g_dssp[16384u*2048u];      // compacted dist hi (zero-init)
__device__ __align__(1024) float  g_scf [16384u*2048u];      // compacted scores fp32
__device__ int g_kidx[BB * KSEQ];
__device__ int g_rank[BB * KSEQ];
__device__ int g_cnt [BB];
__device__ int g_nch3[BB];

__device__ __forceinline__ uint32_t smem_u32(const void* p) {
    uint32_t a;
    asm("{ .reg .u64 t; cvta.to.shared.u64 t, %1; cvt.u32.u64 %0, t; }"
        : "=r"(a) : "l"(p));
    return a;
}
__device__ __forceinline__ void cp16(uint32_t dst, const void* src) {
    asm volatile("cp.async.cg.shared.global [%0], [%1], 16;"
                 :: "r"(dst), "l"(src) : "memory");
}
__device__ __forceinline__ void cp_commit() {
    asm volatile("cp.async.commit_group;" ::: "memory");
}
__device__ __forceinline__ void cp_wait3() {
    asm volatile("cp.async.wait_group 3;" ::: "memory");
}
__device__ __forceinline__ void cp_wait2() {
    asm volatile("cp.async.wait_group 2;" ::: "memory");
}
__device__ __forceinline__ void cp_wait1() {
    asm volatile("cp.async.wait_group 1;" ::: "memory");
}
__device__ __forceinline__ void cp_wait0() {
    asm volatile("cp.async.wait_group 0;" ::: "memory");
}
__device__ __forceinline__ void ldmx4(uint32_t r[4], uint32_t addr) {
    asm volatile("ldmatrix.sync.aligned.m8n8.x4.shared.b16 {%0,%1,%2,%3}, [%4];"
                 : "=r"(r[0]), "=r"(r[1]), "=r"(r[2]), "=r"(r[3]) : "r"(addr));
}
__device__ __forceinline__ void mma16816(float c[4], const uint32_t a[4], const uint32_t* b) {
    asm volatile("mma.sync.aligned.m16n8k16.row.col.f32.f16.f16.f32 "
                 "{%0,%1,%2,%3}, {%4,%5,%6,%7}, {%8,%9}, {%0,%1,%2,%3};"
                 : "+f"(c[0]), "+f"(c[1]), "+f"(c[2]), "+f"(c[3])
                 : "r"(a[0]), "r"(a[1]), "r"(a[2]), "r"(a[3]), "r"(b[0]), "r"(b[1]));
}
__device__ __forceinline__ void splitf(float v, __half& h, __half& l) {
    h = __float2half_rn(v);
    l = __float2half_rn(v - __half2float(h));
}

// ---------------- fp16 mma.sync GEMM (batched over blockIdx.z) ---------------
// NT=2: C = A_h @ (B_h + B_l)^T.   NT=1: C = A_h @ B_h^T.
// BK=32, NSTGT-stage cp.async pipeline, one barrier per chunk.
#define TILEB 10240

// EPI: 0 = fp16 hi out (kW), 1 = scale fp32 (scores), 2 = fp32 (ctx)
template <int EPI, int NT, int NSTGT>
__global__ __launch_bounds__(256, 2) void mma_gemm(
    const __half* __restrict__ A, int lda, long long Abstride,
    const __half* __restrict__ B, long long Bplane, int ldb, long long Bbstride,
    int nch_in,
    float* __restrict__ outF,
    __half* __restrict__ outH, long long obstride,
    float scale, int ldc,
    const int* __restrict__ agidx,
    const int* __restrict__ mcnt, const int* __restrict__ ncnt,
    const int* __restrict__ nchp)
{
    constexpr uint32_t SSTG = (NT + 1) * TILEB;   // stage stride: A + Bh (+ Bl)
    constexpr int D = NSTGT - 1;                  // prefetch distance (chunks)

    const int bz = blockIdx.z;
    if (mcnt && (int)(blockIdx.y * 128) >= mcnt[bz]) return;
    if (ncnt && (int)(blockIdx.x * 128) >= ncnt[bz]) return;
    const int nch = nchp ? nchp[bz] : nch_in;

    extern __shared__ char smem[];
    const uint32_t sb = smem_u32(smem);

    const int tid = threadIdx.x;
    const int lane = tid & 31, wrp = tid >> 5;
    const int wm = (wrp >> 2) * 64, wn = (wrp & 3) * 32;

    const int r0 = tid >> 2, c0 = (tid & 3) * 8;

    const __half* Ab = A + (long long)bz * Abstride;
    const __half* Bb = B + (long long)bz * Bbstride;

    int ar0 = blockIdx.y * 128 + r0, ar1 = ar0 + 64;
    if (agidx) { ar0 = agidx[bz * KSEQ + ar0]; ar1 = agidx[bz * KSEQ + ar1]; }
    const __half* a_src0 = Ab + (long long)ar0 * lda + c0;
    const __half* a_src1 = Ab + (long long)ar1 * lda + c0;

    const __half* b_src0 = Bb + (long long)(blockIdx.x * 128 + r0) * ldb + c0;
    const __half* b_src1 = b_src0 + (long long)64 * ldb;

    const int g = lane >> 3, lr = lane & 7;
    const uint32_t aoff = (uint32_t)(wm + (g & 1) * 8 + lr) * 80 + ((g >> 1) * 16);
    const uint32_t boff = (uint32_t)(wn + ((g >> 1) & 1) * 8 + lr) * 80 + ((g & 1) * 16);

    float acc[4][4][4];
    #pragma unroll
    for (int mt = 0; mt < 4; mt++)
        #pragma unroll
        for (int nt = 0; nt < 4; nt++)
            #pragma unroll
            for (int i = 0; i < 4; i++) acc[mt][nt][i] = 0.f;

    auto load_stage = [&](int buf, int k0) {
        const uint32_t st = sb + buf * SSTG;
        const uint32_t d0 = (uint32_t)r0 * 80 + (c0 * 2);
        const uint32_t d1 = (uint32_t)(r0 + 64) * 80 + (c0 * 2);
        cp16(st + d0, a_src0 + k0);
        cp16(st + d1, a_src1 + k0);
        cp16(st + TILEB + d0, b_src0 + k0);
        cp16(st + TILEB + d1, b_src1 + k0);
        if (NT == 2) {
            cp16(st + 2 * TILEB + d0, b_src0 + k0 + Bplane);
            cp16(st + 2 * TILEB + d1, b_src1 + k0 + Bplane);
        }
        cp_commit();
    };

    #pragma unroll
    for (int s = 0; s < D; s++) load_stage(s, s * 32);

    for (int kt = 0; kt < nch; ++kt) {
        // allow up to NSTGT-2 newest groups pending; chunk kt must be complete
        const int rem = nch - 1 - kt;
        const int pend = rem < (NSTGT - 2) ? rem : (NSTGT - 2);
        if      (pend >= 3) cp_wait3();
        else if (pend == 2) cp_wait2();
        else if (pend == 1) cp_wait1();
        else                cp_wait0();
        __syncthreads();
        // prefetch chunk kt+D into buffer (kt+D)%NSTGT (held chunk kt-1,
        // whose consumers all passed the barrier above)
        if (kt + D < nch) load_stage((kt + D) % NSTGT, (kt + D) * 32);

        const uint32_t st = sb + (kt % NSTGT) * SSTG;
        #pragma unroll
        for (int kk = 0; kk < 2; kk++) {
            uint32_t ah[4][4], bh[2][4], bl[2][4];
            #pragma unroll
            for (int mt = 0; mt < 4; mt++)
                ldmx4(ah[mt], st + mt * (16 * 80) + kk * 32 + aoff);
            #pragma unroll
            for (int nt2 = 0; nt2 < 2; nt2++) {
                const uint32_t bd = st + TILEB + nt2 * (16 * 80) + kk * 32 + boff;
                ldmx4(bh[nt2], bd);
                if (NT == 2) ldmx4(bl[nt2], bd + TILEB);
            }
            #pragma unroll
            for (int mt = 0; mt < 4; mt++)
                #pragma unroll
                for (int nt = 0; nt < 4; nt++) {
                    const uint32_t* ph = &bh[nt >> 1][(nt & 1) * 2];
                    mma16816(acc[mt][nt], ah[mt], ph);
                    if (NT == 2) {
                        const uint32_t* pl = &bl[nt >> 1][(nt & 1) * 2];
                        mma16816(acc[mt][nt], ah[mt], pl);
                    }
                }
        }
    }

    // ---- epilogue ----
    float* outFb = outF + (long long)bz * obstride;
    __half* outHb = outH + (long long)bz * obstride;
    const int rbase = blockIdx.y * 128 + wm + (lane >> 2);
    const int cbase = blockIdx.x * 128 + wn + ((lane & 3) << 1);

    #pragma unroll
    for (int mt = 0; mt < 4; mt++) {
        #pragma unroll
        for (int nt = 0; nt < 4; nt++) {
            const int col = cbase + nt * 8;
            #pragma unroll
            for (int h = 0; h < 2; h++) {
                const int row = rbase + mt * 16 + h * 8;
                float v0 = acc[mt][nt][2 * h], v1 = acc[mt][nt][2 * h + 1];
                const long long o = (long long)row * ldc + col;
                if (EPI == 0) {
                    *(__half2*)(outHb + o) =
                        __halves2half2(__float2half_rn(v0), __float2half_rn(v1));
                } else if (EPI == 1) {
                    *(float2*)(outFb + o) = make_float2(v0 * scale, v1 * scale);
                } else {
                    *(float2*)(outFb + o) = make_float2(v0, v1);
                }
            }
        }
    }
}

// ---------------- mask compaction --------------------------------------------
__global__ void compact_kernel(const int* __restrict__ mask)
{
    const int b = blockIdx.x;
    const int tid = threadIdx.x;
    const int* mrow = mask + b * KSEQ;
    int* kid = g_kidx + b * KSEQ;
    int* rnk = g_rank + b * KSEQ;

    #pragma unroll
    for (int e = 0; e < 8; e++) kid[tid * 8 + e] = 0;
    __syncthreads();

    int m[8], lsum = 0;
    #pragma unroll
    for (int e = 0; e < 8; e++) { m[e] = mrow[tid * 8 + e]; lsum += (m[e] != 0); }

    int s = lsum;
    #pragma unroll
    for (int o = 1; o < 32; o <<= 1) {
        int n = __shfl_up_sync(0xffffffffu, s, o);
        if ((tid & 31) >= o) s += n;
    }
    __shared__ int wsum[8];
    if ((tid & 31) == 31) wsum[tid >> 5] = s;
    __syncthreads();
    int woff = 0, total = 0;
    #pragma unroll
    for (int w = 0; w < 8; w++) {
        if (w < (tid >> 5)) woff += wsum[w];
        total += wsum[w];
    }
    int running = woff + s - lsum;

    #pragma unroll
    for (int e = 0; e < 8; e++) {
        const int p = tid * 8 + e;
        if (m[e]) { kid[running] = p; rnk[p] = running; running++; }
        else rnk[p] = 0;
    }
    if (tid == 0) { g_cnt[b] = total; g_nch3[b] = (total + 31) / 32; }
}

// ---------------- elementwise splits ------------------------------------------
__global__ void split_qk_kernel(const float* __restrict__ q, const float* __restrict__ k)
{
    const float* in = blockIdx.y ? k : q;
    __half* out = blockIdx.y ? g_ksp : g_qsp;
    const long long i = ((long long)blockIdx.x * blockDim.x + threadIdx.x) * 4;
    float4 v = *(const float4*)(in + i);
    out[i]     = __float2half_rn(v.x);
    out[i + 1] = __float2half_rn(v.y);
    out[i + 2] = __float2half_rn(v.z);
    out[i + 3] = __float2half_rn(v.w);
}

template <int LO>
__global__ void split_kernel(const float* __restrict__ in, __half* __restrict__ out,
                             long long plane)
{
    const long long i = ((long long)blockIdx.x * blockDim.x + threadIdx.x) * 4;
    float4 v = *(const float4*)(in + i);
    __half h0, l0, h1, l1, h2, l2, h3, l3;
    splitf(v.x, h0, l0); splitf(v.y, h1, l1); splitf(v.z, h2, l2); splitf(v.w, h3, l3);
    *(__half2*)(out + i)     = __halves2half2(h0, h1);
    *(__half2*)(out + i + 2) = __halves2half2(h2, h3);
    if (LO) {
        *(__half2*)(out + plane + i)     = __halves2half2(l0, l1);
        *(__half2*)(out + plane + i + 2) = __halves2half2(l2, l3);
    }
}

// transpose [R,C] -> [C,R] per batch with row gather, hi plane only
__global__ void tsplit_kernel(const float* __restrict__ in, __half* __restrict__ out,
                              int R, int C, const int* __restrict__ gidx)
{
    __shared__ float t[32][33];
    const int bz = blockIdx.z;
    const long long boff = (long long)bz * R * C;
    const int x = blockIdx.x * 32 + threadIdx.x;
    #pragma unroll
    for (int i = 0; i < 4; ++i) {
        const int y = blockIdx.y * 32 + threadIdx.y + i * 8;
        const int ys = gidx ? gidx[bz * R + y] : y;
        t[threadIdx.y + i * 8][threadIdx.x] = in[boff + (long long)ys * C + x];
    }
    __syncthreads();
    const int xo = blockIdx.y * 32 + threadIdx.x;
    #pragma unroll
    for (int i = 0; i < 4; ++i) {
        const int yo = blockIdx.x * 32 + threadIdx.y + i * 8;
        const float v = t[threadIdx.x][threadIdx.y + i * 8];
        out[boff + (long long)yo * R + xo] = __float2half_rn(v);
    }
}

// ---------------- compacted softmax + scatter (cn-predicated traffic) --------
__global__ void softmax_scatter_kernel(const float* __restrict__ sc,
                                       float* __restrict__ dist,
                                       __half* __restrict__ ds,
                                       const int* __restrict__ mask,
                                       const int* __restrict__ rank,
                                       const int* __restrict__ cntp)
{
    const int bz = blockIdx.y;
    const long long row = (long long)bz * QQ + blockIdx.x;
    const int tid = threadIdx.x;
    const int cn = cntp[bz];
    const float* p = sc + row * (long long)KSEQ;
    const int* mrow = mask + (long long)bz * KSEQ;
    const int* rrow = rank + (long long)bz * KSEQ;

    __shared__ float sm[2048];
    __shared__ float red[8];

    const int j0 = tid * 4, j1 = j0 + 1024;
    float4 v0 = make_float4(0.f, 0.f, 0.f, 0.f);
    float4 v1 = make_float4(0.f, 0.f, 0.f, 0.f);
    if (j0 < cn) v0 = ((const float4*)p)[tid];
    if (j1 < cn) v1 = ((const float4*)p)[tid + 256];

    const float NEG = -1e30f;
    float m = NEG;
    m = fmaxf(m, (j0 + 0 < cn) ? v0.x : NEG);
    m = fmaxf(m, (j0 + 1 < cn) ? v0.y : NEG);
    m = fmaxf(m, (j0 + 2 < cn) ? v0.z : NEG);
    m = fmaxf(m, (j0 + 3 < cn) ? v0.w : NEG);
    m = fmaxf(m, (j1 + 0 < cn) ? v1.x : NEG);
    m = fmaxf(m, (j1 + 1 < cn) ? v1.y : NEG);
    m = fmaxf(m, (j1 + 2 < cn) ? v1.z : NEG);
    m = fmaxf(m, (j1 + 3 < cn) ? v1.w : NEG);
    #pragma unroll
    for (int o = 16; o > 0; o >>= 1) m = fmaxf(m, __shfl_xor_sync(0xffffffffu, m, o));
    if ((tid & 31) == 0) red[tid >> 5] = m;
    __syncthreads();
    m = red[0];
    #pragma unroll
    for (int i = 1; i < 8; i++) m = fmaxf(m, red[i]);
    __syncthreads();

    float e00 = (j0 + 0 < cn) ? __expf(v0.x - m) : 0.f;
    float e01 = (j0 + 1 < cn) ? __expf(v0.y - m) : 0.f;
    float e02 = (j0 + 2 < cn) ? __expf(v0.z - m) : 0.f;
    float e03 = (j0 + 3 < cn) ? __expf(v0.w - m) : 0.f;
    float e10 = (j1 + 0 < cn) ? __expf(v1.x - m) : 0.f;
    float e11 = (j1 + 1 < cn) ? __expf(v1.y - m) : 0.f;
    float e12 = (j1 + 2 < cn) ? __expf(v1.z - m) : 0.f;
    float e13 = (j1 + 3 < cn) ? __expf(v1.w - m) : 0.f;

    float s = e00 + e01 + e02 + e03 + e10 + e11 + e12 + e13;
    #pragma unroll
    for (int o = 16; o > 0; o >>= 1) s += __shfl_xor_sync(0xffffffffu, s, o);
    if ((tid & 31) == 0) red[tid >> 5] = s;
    __syncthreads();
    float tot = red[0];
    #pragma unroll
    for (int i = 1; i < 8; i++) tot += red[i];
    const float inv = 1.0f / tot;

    e00 *= inv; e01 *= inv; e02 *= inv; e03 *= inv;
    e10 *= inv; e11 *= inv; e12 *= inv; e13 *= inv;

    *(float4*)&sm[j0] = make_float4(e00, e01, e02, e03);
    *(float4*)&sm[j1] = make_float4(e10, e11, e12, e13);

    const long long b0o = row * (long long)KSEQ + j0;
    const long long b1o = row * (long long)KSEQ + j1;
    if (j0 < cn) {
        *(__half2*)(ds + b0o)     = __halves2half2(__float2half_rn(e00), __float2half_rn(e01));
        *(__half2*)(ds + b0o + 2) = __halves2half2(__float2half_rn(e02), __float2half_rn(e03));
    }
    if (j1 < cn) {
        *(__half2*)(ds + b1o)     = __halves2half2(__float2half_rn(e10), __float2half_rn(e11));
        *(__half2*)(ds + b1o + 2) = __halves2half2(__float2half_rn(e12), __float2half_rn(e13));
    }

    __syncthreads();

    float* drow = dist + row * (long long)KSEQ;
    #pragma unroll
    for (int h = 0; h < 2; h++) {
        const int idx = tid + h * 256;
        int4 mk = ((const int4*)mrow)[idx];
        int4 rk = ((const int4*)rrow)[idx];
        float4 o;
        o.x = mk.x ? sm[rk.x] : 0.f;
        o.y = mk.y ? sm[rk.y] : 0.f;
        o.z = mk.z ? sm[rk.z] : 0.f;
        o.w = mk.w ? sm[rk.w] : 0.f;
        ((float4*)drow)[idx] = o;
    }
}

// ---------------- host side ---------------------------------------------------
#define SMEM2 (3 * 3 * TILEB)      // 2-term kernel, 3 stages = 92160
#define SMEM1 (4 * 2 * TILEB)      // 1-term kernel, 4 stages = 81920

struct Ctx {
    __half *q, *w, *k, *kw, *vt, *ds;
    float* scf;
    int *kidx, *rank, *cnt, *nch3;
    bool ready;
};
static Ctx& get_ctx()
{
    static Ctx c = {};
    if (!c.ready) {
        cudaGetSymbolAddress((void**)&c.q,    g_qsp);
        cudaGetSymbolAddress((void**)&c.w,    g_wsp);
        cudaGetSymbolAddress((void**)&c.k,    g_ksp);
        cudaGetSymbolAddress((void**)&c.kw,   g_kwsp);
        cudaGetSymbolAddress((void**)&c.vt,   g_vtsp);
        cudaGetSymbolAddress((void**)&c.ds,   g_dssp);
        cudaGetSymbolAddress((void**)&c.scf,  g_scf);
        cudaGetSymbolAddress((void**)&c.kidx, g_kidx);
        cudaGetSymbolAddress((void**)&c.rank, g_rank);
        cudaGetSymbolAddress((void**)&c.cnt,  g_cnt);
        cudaGetSymbolAddress((void**)&c.nch3, g_nch3);
        cudaFuncSetAttribute((const void*)mma_gemm<0, 2, 3>, cudaFuncAttributeMaxDynamicSharedMemorySize, SMEM2);
        cudaFuncSetAttribute((const void*)mma_gemm<1, 1, 4>, cudaFuncAttributeMaxDynamicSharedMemorySize, SMEM1);
        cudaFuncSetAttribute((const void*)mma_gemm<2, 1, 4>, cudaFuncAttributeMaxDynamicSharedMemorySize, SMEM1);
        c.ready = true;
    }
    return c;
}

extern "C" void kernel_launch(void* const* d_in, const int* in_sizes, int n_in,
                              void* d_out, int out_size)
{
    const float* query = (const float*)d_in[0];
    const float* key   = (const float*)d_in[1];
    const float* value = (const float*)d_in[2];
    const int*   mask  = (const int*)d_in[3];
    const float* W     = (const float*)d_in[4];

    float* ctx  = (float*)d_out;                               // [B,Q,D]
    float* dist = ctx + (long long)BB * QQ * DIM;              // [B,Q,K]

    Ctx& C = get_ctx();
    const float scale = 0.044194173824159216f;                 // 1/sqrt(512)

    const long long PW = (long long)512 * 512;
    const long long SB = (long long)QQ * 512;      // per-batch stride, 512-wide
    const long long SD = (long long)QQ * KSEQ;     // per-batch stride, 2048-wide
    const long long SV = (long long)512 * 2048;    // vt per-batch stride

    // single default-stream chain; each launch fills the chip via z-batching
    compact_kernel<<<BB, 256>>>(mask);
    split_qk_kernel<<<dim3(8192, 2), 256>>>(query, key);
    split_kernel<1><<<256, 256>>>(W, C.w, PW);
    tsplit_kernel<<<dim3(16, 64, 8), dim3(32, 8)>>>(value, C.vt, 2048, 512, C.kidx);

    // GEMM1 (2-term, 3-stage): kW = gather(k_h) @ (W_h+W_l)^T, M = cnt[b]
    mma_gemm<0, 2, 3><<<dim3(4, 16, BB), 256, SMEM2>>>(
        C.k, 512, SB, C.w, PW, 512, 0, 16,
        nullptr, C.kw, SB, 0.f, 512,
        C.kidx, C.cnt, nullptr, nullptr);

    // GEMM2 (1-term, 4-stage): scores = q_h @ kW_h^T * scale, N = cnt[b]
    mma_gemm<1, 1, 4><<<dim3(16, 16, BB), 256, SMEM1>>>(
        C.q, 512, SB, C.kw, 0, 512, SB, 16,
        C.scf, nullptr, SD, scale, 2048,
        nullptr, nullptr, C.cnt, nullptr);

    // softmax + scatter + fp16 hi split, all batches
    softmax_scatter_kernel<<<dim3(QQ, BB), 256>>>(
        C.scf, dist, C.ds, mask, C.rank, C.cnt);

    // GEMM3 (1-term, 4-stage): ctx = dist_h @ vt_h^T, K = cnt[b]
    mma_gemm<2, 1, 4><<<dim3(4, 16, BB), 256, SMEM1>>>(
        C.ds, 2048, SD, C.vt, 0, 2048, SV, 64,
        ctx, nullptr, SB, 0.f, 512,
        nullptr, nullptr, nullptr, C.nch3);
}